// round 10
// baseline (speedup 1.0000x reference)
#include <cuda_runtime.h>
#include <cuda_bf16.h>

#define N_NODES 100000
#define E_EDGES 1600000
#define DIN     256
#define DHID    64
#define DOUT    40
#define PROP_STEPS 16

// Scratch (allocation-free rule: __device__ globals)
__device__ float g_Y0[N_NODES * DHID];
__device__ float g_Y1[N_NODES * DHID];
__device__ float g_src[N_NODES * DHID];
__device__ int   g_row_ptr[N_NODES + 1];

// ---------------------------------------------------------------------------
// Kernel 1: CSR row pointers from sorted edge_row via per-thread lower_bound
// ---------------------------------------------------------------------------
__global__ void build_rowptr_kernel(const int* __restrict__ edge_row) {
    int r = blockIdx.x * blockDim.x + threadIdx.x;
    if (r > N_NODES) return;
    int lo = 0, hi = E_EDGES;
    while (lo < hi) {
        int mid = (lo + hi) >> 1;
        if (edge_row[mid] < r) lo = mid + 1; else hi = mid;
    }
    g_row_ptr[r] = lo;
}

// ---------------------------------------------------------------------------
// bf16 hi/lo split helpers for the tensor-core GEMM
// ---------------------------------------------------------------------------
__device__ __forceinline__ void split2(float a, float b, unsigned& hi, unsigned& lo) {
    __nv_bfloat16 ha = __float2bfloat16_rn(a);
    __nv_bfloat16 hb = __float2bfloat16_rn(b);
    float ra = a - __bfloat162float(ha);
    float rb = b - __bfloat162float(hb);
    __nv_bfloat162 H = __halves2bfloat162(ha, hb);
    __nv_bfloat162 L = __halves2bfloat162(__float2bfloat16_rn(ra),
                                          __float2bfloat16_rn(rb));
    hi = reinterpret_cast<unsigned&>(H);
    lo = reinterpret_cast<unsigned&>(L);
}

__device__ __forceinline__ void mma_bf16(float* c, const unsigned* a,
                                         unsigned b0, unsigned b1) {
    asm volatile(
        "mma.sync.aligned.m16n8k16.row.col.f32.bf16.bf16.f32 "
        "{%0,%1,%2,%3}, {%4,%5,%6,%7}, {%8,%9}, {%0,%1,%2,%3};"
        : "+f"(c[0]), "+f"(c[1]), "+f"(c[2]), "+f"(c[3])
        : "r"(a[0]), "r"(a[1]), "r"(a[2]), "r"(a[3]), "r"(b0), "r"(b1));
}

// ---------------------------------------------------------------------------
// Kernel 2 (tensor): h = x @ W1 + b1 ; Y0 = h ; src = 0.5 * diag * h
// ---------------------------------------------------------------------------
__global__ __launch_bounds__(256) void gemm1_tensor_kernel(
    const float* __restrict__ x, const float* __restrict__ W1,
    const float* __restrict__ b1, const float* __restrict__ diag)
{
    __shared__ unsigned sBhi[64][72];
    __shared__ unsigned sBlo[64][72];

    const int tid  = threadIdx.x;
    const int w    = tid >> 5;
    const int lane = tid & 31;
    const int g    = lane >> 2;
    const int tc   = lane & 3;

    const int rowbase = blockIdx.x * 128 + w * 16;
    const int r0 = rowbase + g;
    const int r1 = rowbase + g + 8;
    const int r0c = (r0 < N_NODES) ? r0 : N_NODES - 1;
    const int r1c = (r1 < N_NODES) ? r1 : N_NODES - 1;

    const float* xrow0 = x + (size_t)r0c * DIN;
    const float* xrow1 = x + (size_t)r1c * DIN;

    float c[8][4];
    #pragma unroll
    for (int nt = 0; nt < 8; nt++)
        #pragma unroll
        for (int i = 0; i < 4; i++) c[nt][i] = 0.f;

    for (int chunk = 0; chunk < 2; chunk++) {
        const int k0 = chunk * 128;
        __syncthreads();
        for (int idx = tid; idx < 64 * 64; idx += 256) {
            int pr  = idx >> 6;
            int col = idx & 63;
            float w0 = W1[(k0 + 2 * pr)     * DHID + col];
            float w1 = W1[(k0 + 2 * pr + 1) * DHID + col];
            unsigned hi, lo;
            split2(w0, w1, hi, lo);
            sBhi[pr][col] = hi;
            sBlo[pr][col] = lo;
        }
        __syncthreads();

        #pragma unroll
        for (int j = 0; j < 8; j++) {
            const int kg = k0 + j * 16;
            float2 f00 = *(const float2*)(xrow0 + kg + 2 * tc);
            float2 f10 = *(const float2*)(xrow1 + kg + 2 * tc);
            float2 f01 = *(const float2*)(xrow0 + kg + 2 * tc + 8);
            float2 f11 = *(const float2*)(xrow1 + kg + 2 * tc + 8);
            unsigned ahi[4], alo[4];
            split2(f00.x, f00.y, ahi[0], alo[0]);
            split2(f10.x, f10.y, ahi[1], alo[1]);
            split2(f01.x, f01.y, ahi[2], alo[2]);
            split2(f11.x, f11.y, ahi[3], alo[3]);

            const int j8 = j * 8;
            #pragma unroll
            for (int nt = 0; nt < 8; nt++) {
                const int n0 = nt * 8;
                unsigned bh0 = sBhi[j8 + tc][n0 + g];
                unsigned bh1 = sBhi[j8 + tc + 4][n0 + g];
                unsigned bl0 = sBlo[j8 + tc][n0 + g];
                unsigned bl1 = sBlo[j8 + tc + 4][n0 + g];
                mma_bf16(c[nt], ahi, bh0, bh1);
                mma_bf16(c[nt], ahi, bl0, bl1);
                mma_bf16(c[nt], alo, bh0, bh1);
            }
        }
    }

    const float dv0 = (r0 < N_NODES) ? 0.5f * diag[r0] : 0.f;
    const float dv1 = (r1 < N_NODES) ? 0.5f * diag[r1] : 0.f;
    #pragma unroll
    for (int nt = 0; nt < 8; nt++) {
        const int col = nt * 8 + 2 * tc;
        float bb0 = b1[col], bb1 = b1[col + 1];
        if (r0 < N_NODES) {
            float h0 = c[nt][0] + bb0;
            float h1 = c[nt][1] + bb1;
            g_Y0[r0 * DHID + col]      = h0;
            g_Y0[r0 * DHID + col + 1]  = h1;
            g_src[r0 * DHID + col]     = dv0 * h0;
            g_src[r0 * DHID + col + 1] = dv0 * h1;
        }
        if (r1 < N_NODES) {
            float h2 = c[nt][2] + bb0;
            float h3 = c[nt][3] + bb1;
            g_Y0[r1 * DHID + col]      = h2;
            g_Y0[r1 * DHID + col + 1]  = h3;
            g_src[r1 * DHID + col]     = dv1 * h2;
            g_src[r1 * DHID + col + 1] = dv1 * h3;
        }
    }
}

// ---------------------------------------------------------------------------
// Kernel 3: one propagation step. TWO rows per warp, interleaved 4-edge
// unrolls => 8 independent gathers in flight per warp (2x the R2 MLP).
// Joint-loop bounds are identical across all 32 lanes: zero divergence.
// Tails use the proven R2 loop per row. Lane owns 2 columns (float2).
// ---------------------------------------------------------------------------
__global__ __launch_bounds__(256) void prop_kernel(
    const int* __restrict__ ecol, const float* __restrict__ evalv, int phase)
{
    const float* __restrict__ Yin  = phase ? g_Y1 : g_Y0;
    float*       __restrict__ Yout = phase ? g_Y0 : g_Y1;

    int wp = (blockIdx.x * blockDim.x + threadIdx.x) >> 5;
    int rA = wp * 2;
    if (rA >= N_NODES) return;
    int rB = rA + 1;                       // N_NODES even -> always valid
    int lane = threadIdx.x & 31;

    int eA   = g_row_ptr[rA];
    int endA = g_row_ptr[rA + 1];
    int eB   = endA;                        // CSR contiguity
    int endB = g_row_ptr[rB + 1];

    float axA = 0.f, ayA = 0.f, axB = 0.f, ayB = 0.f;

    // Joint loop: 4 edges of each row per iteration, 8 gathers in flight
    while (eA + 4 <= endA && eB + 4 <= endB) {
        int   cA0 = ecol[eA],  cA1 = ecol[eA + 1], cA2 = ecol[eA + 2], cA3 = ecol[eA + 3];
        int   cB0 = ecol[eB],  cB1 = ecol[eB + 1], cB2 = ecol[eB + 2], cB3 = ecol[eB + 3];
        float vA0 = evalv[eA], vA1 = evalv[eA + 1], vA2 = evalv[eA + 2], vA3 = evalv[eA + 3];
        float vB0 = evalv[eB], vB1 = evalv[eB + 1], vB2 = evalv[eB + 2], vB3 = evalv[eB + 3];
        float2 yA0 = *(const float2*)&Yin[cA0 * DHID + lane * 2];
        float2 yA1 = *(const float2*)&Yin[cA1 * DHID + lane * 2];
        float2 yA2 = *(const float2*)&Yin[cA2 * DHID + lane * 2];
        float2 yA3 = *(const float2*)&Yin[cA3 * DHID + lane * 2];
        float2 yB0 = *(const float2*)&Yin[cB0 * DHID + lane * 2];
        float2 yB1 = *(const float2*)&Yin[cB1 * DHID + lane * 2];
        float2 yB2 = *(const float2*)&Yin[cB2 * DHID + lane * 2];
        float2 yB3 = *(const float2*)&Yin[cB3 * DHID + lane * 2];
        axA += vA0 * yA0.x + vA1 * yA1.x + vA2 * yA2.x + vA3 * yA3.x;
        ayA += vA0 * yA0.y + vA1 * yA1.y + vA2 * yA2.y + vA3 * yA3.y;
        axB += vB0 * yB0.x + vB1 * yB1.x + vB2 * yB2.x + vB3 * yB3.x;
        ayB += vB0 * yB0.y + vB1 * yB1.y + vB2 * yB2.y + vB3 * yB3.y;
        eA += 4; eB += 4;
    }

    // Row A tail (R2 loop)
    for (; eA + 4 <= endA; eA += 4) {
        int   c0 = ecol[eA],  c1 = ecol[eA + 1], c2 = ecol[eA + 2], c3 = ecol[eA + 3];
        float v0 = evalv[eA], v1 = evalv[eA + 1], v2 = evalv[eA + 2], v3 = evalv[eA + 3];
        float2 y0 = *(const float2*)&Yin[c0 * DHID + lane * 2];
        float2 y1 = *(const float2*)&Yin[c1 * DHID + lane * 2];
        float2 y2 = *(const float2*)&Yin[c2 * DHID + lane * 2];
        float2 y3 = *(const float2*)&Yin[c3 * DHID + lane * 2];
        axA += v0 * y0.x + v1 * y1.x + v2 * y2.x + v3 * y3.x;
        ayA += v0 * y0.y + v1 * y1.y + v2 * y2.y + v3 * y3.y;
    }
    for (; eA < endA; eA++) {
        int   c = ecol[eA];
        float v = evalv[eA];
        float2 y = *(const float2*)&Yin[c * DHID + lane * 2];
        axA += v * y.x; ayA += v * y.y;
    }
    // Row B tail (R2 loop)
    for (; eB + 4 <= endB; eB += 4) {
        int   c0 = ecol[eB],  c1 = ecol[eB + 1], c2 = ecol[eB + 2], c3 = ecol[eB + 3];
        float v0 = evalv[eB], v1 = evalv[eB + 1], v2 = evalv[eB + 2], v3 = evalv[eB + 3];
        float2 y0 = *(const float2*)&Yin[c0 * DHID + lane * 2];
        float2 y1 = *(const float2*)&Yin[c1 * DHID + lane * 2];
        float2 y2 = *(const float2*)&Yin[c2 * DHID + lane * 2];
        float2 y3 = *(const float2*)&Yin[c3 * DHID + lane * 2];
        axB += v0 * y0.x + v1 * y1.x + v2 * y2.x + v3 * y3.x;
        ayB += v0 * y0.y + v1 * y1.y + v2 * y2.y + v3 * y3.y;
    }
    for (; eB < endB; eB++) {
        int   c = ecol[eB];
        float v = evalv[eB];
        float2 y = *(const float2*)&Yin[c * DHID + lane * 2];
        axB += v * y.x; ayB += v * y.y;
    }

    // Epilogue: both rows
    float2 yrA = *(const float2*)&Yin[rA * DHID + lane * 2];
    float2 sA  = *(const float2*)&g_src[rA * DHID + lane * 2];
    float2 oA;
    oA.x = 0.5f * (yrA.x + axA) + sA.x;
    oA.y = 0.5f * (yrA.y + ayA) + sA.y;
    *(float2*)&Yout[rA * DHID + lane * 2] = oA;

    float2 yrB = *(const float2*)&Yin[rB * DHID + lane * 2];
    float2 sB  = *(const float2*)&g_src[rB * DHID + lane * 2];
    float2 oB;
    oB.x = 0.5f * (yrB.x + axB) + sB.x;
    oB.y = 0.5f * (yrB.y + ayB) + sB.y;
    *(float2*)&Yout[rB * DHID + lane * 2] = oB;
}

// ---------------------------------------------------------------------------
// Kernel 4: out = relu(Y) @ W2 + b2.
// ---------------------------------------------------------------------------
__global__ __launch_bounds__(256) void mlp2_kernel(
    const float* __restrict__ W2, const float* __restrict__ b2,
    float* __restrict__ out)
{
    __shared__ float w2s[64][41];
    __shared__ float ys[64][65];
    __shared__ float b2s[DOUT];

    const int tid = threadIdx.x;
    const int row0 = blockIdx.x * 64;

    for (int idx = tid; idx < DHID * DOUT; idx += 256)
        w2s[idx / DOUT][idx % DOUT] = W2[idx];
    if (tid < DOUT) b2s[tid] = b2[tid];

    #pragma unroll
    for (int i = 0; i < 16; i++) {
        int idx = tid + i * 256;
        int r = idx >> 6, c = idx & 63;
        int gr = row0 + r;
        ys[r][c] = (gr < N_NODES) ? fmaxf(g_Y0[gr * DHID + c], 0.f) : 0.f;
    }
    __syncthreads();

    const int row = tid >> 2;
    const int cg  = tid & 3;
    float acc[10];
    #pragma unroll
    for (int i = 0; i < 10; i++) acc[i] = b2s[cg * 10 + i];

    #pragma unroll 8
    for (int j = 0; j < DHID; j++) {
        float yv = ys[row][j];
        #pragma unroll
        for (int i = 0; i < 10; i++)
            acc[i] += yv * w2s[j][cg * 10 + i];
    }

    int gr = row0 + row;
    if (gr < N_NODES) {
        #pragma unroll
        for (int i = 0; i < 10; i++)
            out[gr * DOUT + cg * 10 + i] = acc[i];
    }
}

// ---------------------------------------------------------------------------
extern "C" void kernel_launch(void* const* d_in, const int* in_sizes, int n_in,
                              void* d_out, int out_size)
{
    const float* x     = (const float*)d_in[0];
    const int*   erow  = (const int*)  d_in[1];
    const int*   ecol  = (const int*)  d_in[2];
    const float* evalv = (const float*)d_in[3];
    const float* diag  = (const float*)d_in[4];
    const float* W1    = (const float*)d_in[5];
    const float* b1    = (const float*)d_in[6];
    const float* W2    = (const float*)d_in[7];
    const float* b2    = (const float*)d_in[8];
    float* out = (float*)d_out;

    build_rowptr_kernel<<<(N_NODES + 1 + 255) / 256, 256>>>(erow);

    int gemm_blocks = (N_NODES + 127) / 128;
    gemm1_tensor_kernel<<<gemm_blocks, 256>>>(x, W1, b1, diag);

    // two rows per warp: N/2 warps total
    int prop_blocks = ((N_NODES / 2) * 32 + 255) / 256;
    for (int s = 0; s < PROP_STEPS; s++) {
        prop_kernel<<<prop_blocks, 256>>>(ecol, evalv, s & 1);
    }

    int mlp_blocks = (N_NODES + 63) / 64;
    mlp2_kernel<<<mlp_blocks, 256>>>(W2, b2, out);
}